// round 2
// baseline (speedup 1.0000x reference)
#include <cuda_runtime.h>
#include <cstdint>

#define DIM 192
#define NV (DIM * DIM * DIM)
#define NPIX 125.0f
#define EPS 1e-5f

// Scratch: 5 fields after W-sum, 5 fields after H-sum. Static device globals
// (no dynamic allocation allowed).
__device__ float g_s1[5][NV];
__device__ float g_s2[5][NV];

// ---------------------------------------------------------------------------
// Pass 1: 5-tap box sum along W (contiguous axis) of {m, f, m*m, f*f, m*f}.
// One block per (z,y) row; row staged in shared memory.
// ---------------------------------------------------------------------------
__global__ void __launch_bounds__(DIM) pass1_wsum(const float* __restrict__ m,
                                                  const float* __restrict__ f) {
    __shared__ float sm[DIM];
    __shared__ float sf[DIM];
    const int row = blockIdx.x;          // z*DIM + y
    const int x = threadIdx.x;
    const size_t base = (size_t)row * DIM;

    sm[x] = m[base + x];
    sf[x] = f[base + x];
    __syncthreads();

    float s_m = 0.f, s_f = 0.f, s_mm = 0.f, s_ff = 0.f, s_mf = 0.f;
#pragma unroll
    for (int dx = -2; dx <= 2; dx++) {
        int xx = x + dx;
        if ((unsigned)xx < DIM) {
            float a = sm[xx];
            float b = sf[xx];
            s_m += a;
            s_f += b;
            s_mm += a * a;
            s_ff += b * b;
            s_mf += a * b;
        }
    }
    const size_t i = base + x;
    g_s1[0][i] = s_m;
    g_s1[1][i] = s_f;
    g_s1[2][i] = s_mm;
    g_s1[3][i] = s_ff;
    g_s1[4][i] = s_mf;
}

// ---------------------------------------------------------------------------
// Pass 2: 5-tap box sum along H (stride DIM) for all 5 fields.
// ---------------------------------------------------------------------------
__global__ void __launch_bounds__(256) pass2_hsum() {
    const int i = blockIdx.x * blockDim.x + threadIdx.x;
    if (i >= NV) return;
    const int y = (i / DIM) % DIM;

    float acc0 = 0.f, acc1 = 0.f, acc2 = 0.f, acc3 = 0.f, acc4 = 0.f;
#pragma unroll
    for (int dy = -2; dy <= 2; dy++) {
        int yy = y + dy;
        if ((unsigned)yy < DIM) {
            int j = i + dy * DIM;
            acc0 += g_s1[0][j];
            acc1 += g_s1[1][j];
            acc2 += g_s1[2][j];
            acc3 += g_s1[3][j];
            acc4 += g_s1[4][j];
        }
    }
    g_s2[0][i] = acc0;
    g_s2[1][i] = acc1;
    g_s2[2][i] = acc2;
    g_s2[3][i] = acc3;
    g_s2[4][i] = acc4;
}

// ---------------------------------------------------------------------------
// Pass 3: 5-tap box sum along D (stride DIM*DIM), then fused NCC factor,
// image gradients (jnp.gradient semantics), union mask, and output write.
// Output layout: [3, DIM, DIM, DIM] (channels = grad along D, H, W).
// ---------------------------------------------------------------------------
__global__ void __launch_bounds__(256) pass3_final(const float* __restrict__ m,
                                                   const float* __restrict__ f,
                                                   const int* __restrict__ mmask,
                                                   const int* __restrict__ fmask,
                                                   float* __restrict__ out) {
    const int i = blockIdx.x * blockDim.x + threadIdx.x;
    if (i >= NV) return;
    const int x = i % DIM;
    const int y = (i / DIM) % DIM;
    const int z = i / (DIM * DIM);
    const int S = DIM * DIM;

    float sum_m = 0.f, sum_f = 0.f, sum_mm = 0.f, sum_ff = 0.f, sum_mf = 0.f;
#pragma unroll
    for (int dz = -2; dz <= 2; dz++) {
        int zz = z + dz;
        if ((unsigned)zz < DIM) {
            int j = i + dz * S;
            sum_m += g_s2[0][j];
            sum_f += g_s2[1][j];
            sum_mm += g_s2[2][j];
            sum_ff += g_s2[3][j];
            sum_mf += g_s2[4][j];
        }
    }

    // NCC factor (replicates reference expression structure)
    const float moving_mean = sum_m / NPIX;
    const float fixed_mean = sum_f / NPIX;
    const float var_m = sum_mm - 2.0f * moving_mean * sum_m + NPIX * moving_mean * moving_mean;
    const float var_f = sum_ff - 2.0f * fixed_mean * sum_f + NPIX * fixed_mean * fixed_mean;
    const float var_mf = var_m * var_f;
    const float cross = sum_mf - fixed_mean * sum_m - moving_mean * sum_f
                        + NPIX * moving_mean * fixed_mean;

    const float mv = m[i];
    const float fv = f[i];
    const float mc = mv - moving_mean;
    const float fc = fv - fixed_mean;

    const bool valid = (var_mf > EPS) && (var_f > EPS) && (fc != 0.0f) && (mc != 0.0f);
    float factor = 0.0f;
    if (valid) {
        factor = 2.0f * cross / var_mf * (mc - cross * fc / var_f);
    }

    const float u = ((mmask[i] | fmask[i]) != 0) ? 1.0f : 0.0f;
    // out = -factor * 0.5 * union * (grad_m + grad_f)
    const float scale = -0.5f * factor * u;

    // Gradients: central diff interior, one-sided at edges (spacing = 1).
    float gD, gH, gW;
    // --- axis D ---
    {
        float gm, gf;
        if (z == 0) {
            gm = m[i + S] - mv;
            gf = f[i + S] - fv;
        } else if (z == DIM - 1) {
            gm = mv - m[i - S];
            gf = fv - f[i - S];
        } else {
            gm = 0.5f * (m[i + S] - m[i - S]);
            gf = 0.5f * (f[i + S] - f[i - S]);
        }
        gD = gm + gf;
    }
    // --- axis H ---
    {
        float gm, gf;
        if (y == 0) {
            gm = m[i + DIM] - mv;
            gf = f[i + DIM] - fv;
        } else if (y == DIM - 1) {
            gm = mv - m[i - DIM];
            gf = fv - f[i - DIM];
        } else {
            gm = 0.5f * (m[i + DIM] - m[i - DIM]);
            gf = 0.5f * (f[i + DIM] - f[i - DIM]);
        }
        gH = gm + gf;
    }
    // --- axis W ---
    {
        float gm, gf;
        if (x == 0) {
            gm = m[i + 1] - mv;
            gf = f[i + 1] - fv;
        } else if (x == DIM - 1) {
            gm = mv - m[i - 1];
            gf = fv - f[i - 1];
        } else {
            gm = 0.5f * (m[i + 1] - m[i - 1]);
            gf = 0.5f * (f[i + 1] - f[i - 1]);
        }
        gW = gm + gf;
    }

    out[0 * NV + i] = scale * gD;
    out[1 * NV + i] = scale * gH;
    out[2 * NV + i] = scale * gW;
}

extern "C" void kernel_launch(void* const* d_in, const int* in_sizes, int n_in,
                              void* d_out, int out_size) {
    const float* moving = (const float*)d_in[0];
    const float* fixed_ = (const float*)d_in[1];
    const int* mmask = (const int*)d_in[2];
    const int* fmask = (const int*)d_in[3];
    float* out = (float*)d_out;

    pass1_wsum<<<DIM * DIM, DIM>>>(moving, fixed_);
    const int threads = 256;
    const int blocks = (NV + threads - 1) / threads;
    pass2_hsum<<<blocks, threads>>>();
    pass3_final<<<blocks, threads>>>(moving, fixed_, mmask, fmask, out);
}

// round 4
// speedup vs baseline: 1.5585x; 1.5585x over previous
#include <cuda_runtime.h>
#include <cstdint>

#define DIM 192
#define SLICE (DIM * DIM)
#define NV (DIM * DIM * DIM)
#define NPIX 125.0f
#define EPS 1e-5f

#define TX 32
#define TY 8
#define ZCHUNK 48
#define NSTEPS (ZCHUNK + 4)   // 52 planes touched per chunk

#define TLX (TX + 4)          // 36 (x halo 2)
#define TLY (TY + 4)          // 12 (y halo 2)
#define TLXP 37               // padded row
#define MFX (TX + 2)          // 34 (x halo 1 for gradients)
#define MFY (TY + 2)          // 10
#define MFXP 35

__global__ void __launch_bounds__(256) ncc_fused(
    const float* __restrict__ m, const float* __restrict__ f,
    const int* __restrict__ mmask, const int* __restrict__ fmask,
    float* __restrict__ out) {
  __shared__ float2 tile[TLY][TLXP];   // m,f plane with halo 2
  __shared__ float4 w4[TLY][TX];       // W-sums: m,f,mm,ff
  __shared__ float w1[TLY][TX + 1];    // W-sums: mf
  __shared__ float2 mfr[4][MFY][MFXP]; // m,f ring (halo 1) for gradients

  const int tid = threadIdx.x;
  const int tx = tid & 31;
  const int ty = tid >> 5;
  const int bx = blockIdx.x, by = blockIdx.y, bz = blockIdx.z;
  const int z0 = bz * ZCHUNK;
  const int zend = z0 + ZCHUNK - 1;
  const int gx = bx * TX + tx;
  const int gy = by * TY + ty;

  // Sliding 5-plane window per field: ring[phase][field] holds the H-sum from
  // 5 steps ago (phase = step % 5, compile-time in the unrolled inner loop).
  float ring[5][5];
  float acc[5];
#pragma unroll
  for (int p = 0; p < 5; p++) {
    acc[p] = 0.f;
#pragma unroll
    for (int q = 0; q < 5; q++) ring[p][q] = 0.f;
  }

  // 11 * 5 = 55 steps; steps >= NSTEPS (52) are no-ops for loading but still
  // slide the window (adding zero planes), which is the correct edge behavior.
#pragma unroll 1
  for (int o = 0; o < 11; o++) {
#pragma unroll
    for (int ph = 0; ph < 5; ph++) {
      const int step = o * 5 + ph;
      const int zp = z0 - 2 + step;
      float h[5] = {0.f, 0.f, 0.f, 0.f, 0.f};

      if (step < NSTEPS && zp >= 0 && zp < DIM) {
        __syncthreads();  // prior epilogue's mfr/w4 reads complete
        const size_t pbase = (size_t)zp * SLICE;
        // Stage m,f plane tile with halo 2.
        for (int idx = tid; idx < TLX * TLY; idx += 256) {
          int lx = idx % TLX, ly = idx / TLX;
          int ggx = bx * TX - 2 + lx, ggy = by * TY - 2 + ly;
          float a = 0.f, b = 0.f;
          if ((unsigned)ggx < DIM && (unsigned)ggy < DIM) {
            size_t off = pbase + (size_t)ggy * DIM + ggx;
            a = m[off];
            b = f[off];
          }
          tile[ly][lx] = make_float2(a, b);
        }
        __syncthreads();
        // W-direction 5-tap sums of the 5 product fields.
        for (int idx = tid; idx < TX * TLY; idx += 256) {
          int xi = idx & 31, ly = idx >> 5;
          float sm = 0.f, sf = 0.f, smm = 0.f, sff = 0.f, smf = 0.f;
#pragma unroll
          for (int d = 0; d < 5; d++) {
            float2 ab = tile[ly][xi + d];
            sm += ab.x;
            sf += ab.y;
            smm += ab.x * ab.x;
            sff += ab.y * ab.y;
            smf += ab.x * ab.y;
          }
          w4[ly][xi] = make_float4(sm, sf, smm, sff);
          w1[ly][xi] = smf;
        }
        // Keep m,f plane (halo 1) in the gradient ring.
        for (int idx = tid; idx < MFX * MFY; idx += 256) {
          int lx = idx % MFX, ly = idx / MFX;
          mfr[zp & 3][ly][lx] = tile[ly + 1][lx + 1];
        }
        __syncthreads();
        // H-direction 5-tap sums for this thread's (x,y).
#pragma unroll
        for (int d = 0; d < 5; d++) {
          float4 v = w4[ty + d][tx];
          h[0] += v.x;
          h[1] += v.y;
          h[2] += v.z;
          h[3] += v.w;
          h[4] += w1[ty + d][tx];
        }
      }

      // Slide the D-window: add new plane, drop the plane from 5 steps ago.
#pragma unroll
      for (int q = 0; q < 5; q++) {
        acc[q] += h[q] - ring[ph][q];
        ring[ph][q] = h[q];
      }

      const int z_out = zp - 2;
      if (z_out >= z0 && z_out <= zend) {
        const float sum_m = acc[0], sum_f = acc[1], sum_mm = acc[2],
                    sum_ff = acc[3], sum_mf = acc[4];
        const float mmean = sum_m / NPIX;
        const float fmean = sum_f / NPIX;
        const float var_m = sum_mm - 2.0f * mmean * sum_m + NPIX * mmean * mmean;
        const float var_f = sum_ff - 2.0f * fmean * sum_f + NPIX * fmean * fmean;
        const float var_mf = var_m * var_f;
        const float cross =
            sum_mf - fmean * sum_m - mmean * sum_f + NPIX * mmean * fmean;

        const int lx = tx + 1, lyy = ty + 1;
        const int pc = z_out & 3, pm = (z_out - 1) & 3, pp = (z_out + 1) & 3;
        float2 c = mfr[pc][lyy][lx];
        float mc = c.x - mmean, fc = c.y - fmean;

        bool valid =
            (var_mf > EPS) && (var_f > EPS) && (fc != 0.0f) && (mc != 0.0f);
        float factor = 0.0f;
        if (valid) factor = 2.0f * cross / var_mf * (mc - cross * fc / var_f);

        size_t i = (size_t)z_out * SLICE + (size_t)gy * DIM + gx;
        float u = ((mmask[i] | fmask[i]) != 0) ? 1.0f : 0.0f;
        float scale = -0.5f * factor * u;

        // jnp.gradient: central diff interior, one-sided edges.
        float gD, gH, gW;
        if (z_out == 0) {
          float2 a = mfr[pp][lyy][lx];
          gD = (a.x - c.x) + (a.y - c.y);
        } else if (z_out == DIM - 1) {
          float2 b = mfr[pm][lyy][lx];
          gD = (c.x - b.x) + (c.y - b.y);
        } else {
          float2 a = mfr[pp][lyy][lx];
          float2 b = mfr[pm][lyy][lx];
          gD = 0.5f * (a.x - b.x) + 0.5f * (a.y - b.y);
        }
        if (gy == 0) {
          float2 a = mfr[pc][lyy + 1][lx];
          gH = (a.x - c.x) + (a.y - c.y);
        } else if (gy == DIM - 1) {
          float2 b = mfr[pc][lyy - 1][lx];
          gH = (c.x - b.x) + (c.y - b.y);
        } else {
          float2 a = mfr[pc][lyy + 1][lx];
          float2 b = mfr[pc][lyy - 1][lx];
          gH = 0.5f * (a.x - b.x) + 0.5f * (a.y - b.y);
        }
        if (gx == 0) {
          float2 a = mfr[pc][lyy][lx + 1];
          gW = (a.x - c.x) + (a.y - c.y);
        } else if (gx == DIM - 1) {
          float2 b = mfr[pc][lyy][lx - 1];
          gW = (c.x - b.x) + (c.y - b.y);
        } else {
          float2 a = mfr[pc][lyy][lx + 1];
          float2 b = mfr[pc][lyy][lx - 1];
          gW = 0.5f * (a.x - b.x) + 0.5f * (a.y - b.y);
        }

        out[i] = scale * gD;
        out[(size_t)NV + i] = scale * gH;
        out[2 * (size_t)NV + i] = scale * gW;
      }
    }
  }
}

extern "C" void kernel_launch(void* const* d_in, const int* in_sizes, int n_in,
                              void* d_out, int out_size) {
  const float* moving = (const float*)d_in[0];
  const float* fixed_ = (const float*)d_in[1];
  const int* mmask = (const int*)d_in[2];
  const int* fmask = (const int*)d_in[3];
  float* out = (float*)d_out;

  dim3 grid(DIM / TX, DIM / TY, DIM / ZCHUNK);  // 6 x 24 x 4 = 576 blocks
  ncc_fused<<<grid, 256>>>(moving, fixed_, mmask, fmask, out);
}

// round 10
// speedup vs baseline: 1.7927x; 1.1503x over previous
#include <cuda_runtime.h>
#include <cstdint>

#define DIM 192
#define SLICE (DIM * DIM)
#define NV (DIM * DIM * DIM)
#define NPIX 125.0f
#define EPS 1e-5f

#define TX 32
#define TY 8
#define ZCHUNK 48
#define NSTEPS (ZCHUNK + 4)   // 52 planes swept per chunk (halo 2 each side)

#define TLX (TX + 4)          // 36 (x halo 2)
#define TLY (TY + 4)          // 12 (y halo 2)
#define TLXP 37               // padded row
#define NSTAGE (TLX * TLY)    // 432 staging elements

__global__ void __launch_bounds__(256) ncc_fused(
    const float* __restrict__ m, const float* __restrict__ f,
    const int* __restrict__ mmask, const int* __restrict__ fmask,
    float* __restrict__ out) {
  // 5-deep ring of (m,f) plane tiles with halo 2 — serves both the W-sum and
  // the z/y/x gradients. 5*12*37*8B = 17.8 KB.
  __shared__ float2 ring[5][TLY][TLXP];
  __shared__ float4 w4[TLY][TX];      // W-sums: m,f,mm,ff
  __shared__ float w1[TLY][TX + 1];   // W-sums: mf

  const int tid = threadIdx.x;
  const int tx = tid & 31;
  const int ty = tid >> 5;
  const int bx = blockIdx.x, by = blockIdx.y, bz = blockIdx.z;
  const int z0 = bz * ZCHUNK;
  const int zend = z0 + ZCHUNK - 1;
  const int gx = bx * TX + tx;
  const int gy = by * TY + ty;

  // Two staging slots per thread (NSTAGE=432, 256 threads).
  const int lx0 = tid % TLX, ly0 = tid / TLX;
  const int idx1 = tid + 256;
  const bool ok1 = idx1 < NSTAGE;
  const int lx1 = ok1 ? (idx1 % TLX) : 0, ly1 = ok1 ? (idx1 / TLX) : 0;
  const int ggx0 = bx * TX - 2 + lx0, ggy0 = by * TY - 2 + ly0;
  const int ggx1 = bx * TX - 2 + lx1, ggy1 = by * TY - 2 + ly1;
  const bool in0 = (unsigned)ggx0 < DIM && (unsigned)ggy0 < DIM;
  const bool in1 = ok1 && (unsigned)ggx1 < DIM && (unsigned)ggy1 < DIM;
  const size_t off0 = (size_t)ggy0 * DIM + ggx0;
  const size_t off1 = (size_t)ggy1 * DIM + ggx1;
  const size_t moff = (size_t)gy * DIM + gx;

  // Prefetch registers: next plane's data + next output's masks.
  float pa0 = 0.f, pb0 = 0.f, pa1 = 0.f, pb1 = 0.f;
  int pmm = 0, pff = 0;
  {
    const int zp = z0 - 2;  // plane for step 0
    if (zp >= 0) {
      const size_t pb_ = (size_t)zp * SLICE;
      if (in0) { pa0 = m[pb_ + off0]; pb0 = f[pb_ + off0]; }
      if (in1) { pa1 = m[pb_ + off1]; pb1 = f[pb_ + off1]; }
    }
  }

  // Sliding 5-plane D-window as shift registers (oldest = s0, newest = s4).
  float s0_0 = 0.f, s0_1 = 0.f, s0_2 = 0.f, s0_3 = 0.f, s0_4 = 0.f;
  float s1_0 = 0.f, s1_1 = 0.f, s1_2 = 0.f, s1_3 = 0.f, s1_4 = 0.f;
  float s2_0 = 0.f, s2_1 = 0.f, s2_2 = 0.f, s2_3 = 0.f, s2_4 = 0.f;
  float s3_0 = 0.f, s3_1 = 0.f, s3_2 = 0.f, s3_3 = 0.f, s3_4 = 0.f;
  float s4_0 = 0.f, s4_1 = 0.f, s4_2 = 0.f, s4_3 = 0.f, s4_4 = 0.f;
  float acc0 = 0.f, acc1 = 0.f, acc2 = 0.f, acc3 = 0.f, acc4 = 0.f;

#pragma unroll 1
  for (int step = 0; step < NSTEPS; step++) {
    const int zp = z0 - 2 + step;
    const bool active = (zp >= 0) && (zp < DIM);
    // Capture this step's masks before the prefetch overwrites them.
    const int cmm = pmm, cff = pff;
    float h0 = 0.f, h1 = 0.f, h2 = 0.f, h3 = 0.f, h4 = 0.f;

    if (active) {
      const int s = zp % 5;
      // Stage the prefetched plane into the ring slot.
      ring[s][ly0][lx0] = make_float2(pa0, pb0);
      if (ok1) ring[s][ly1][lx1] = make_float2(pa1, pb1);
      __syncthreads();
      // W-direction 5-tap sums of the 5 product fields.
      for (int idx = tid; idx < TX * TLY; idx += 256) {
        const int xi = idx & 31, ly = idx >> 5;
        float sm = 0.f, sf = 0.f, smm = 0.f, sff = 0.f, smf = 0.f;
#pragma unroll
        for (int d = 0; d < 5; d++) {
          float2 ab = ring[s][ly][xi + d];
          sm += ab.x;
          sf += ab.y;
          smm += ab.x * ab.x;
          sff += ab.y * ab.y;
          smf += ab.x * ab.y;
        }
        w4[ly][xi] = make_float4(sm, sf, smm, sff);
        w1[ly][xi] = smf;
      }
    }

    // Prefetch next plane + next output's masks (overlaps the W-sum work).
    {
      const int zpn = zp + 1;
      if (step + 1 < NSTEPS && zpn >= 0 && zpn < DIM) {
        const size_t pb_ = (size_t)zpn * SLICE;
        if (in0) { pa0 = m[pb_ + off0]; pb0 = f[pb_ + off0]; }
        if (in1) { pa1 = m[pb_ + off1]; pb1 = f[pb_ + off1]; }
      }
      const int zon = zpn - 2;
      if (zon >= z0 && zon <= zend) {
        const size_t mb = (size_t)zon * SLICE + moff;
        pmm = mmask[mb];
        pff = fmask[mb];
      }
    }

    if (active) {
      __syncthreads();
      // H-direction 5-tap sums for this thread's (x,y).
#pragma unroll
      for (int d = 0; d < 5; d++) {
        float4 v = w4[ty + d][tx];
        h0 += v.x;
        h1 += v.y;
        h2 += v.z;
        h3 += v.w;
        h4 += w1[ty + d][tx];
      }
    }

    // Slide the D-window: add the new plane, drop the 5-steps-old plane.
    acc0 += h0 - s0_0; acc1 += h1 - s0_1; acc2 += h2 - s0_2;
    acc3 += h3 - s0_3; acc4 += h4 - s0_4;
    s0_0 = s1_0; s0_1 = s1_1; s0_2 = s1_2; s0_3 = s1_3; s0_4 = s1_4;
    s1_0 = s2_0; s1_1 = s2_1; s1_2 = s2_2; s1_3 = s2_3; s1_4 = s2_4;
    s2_0 = s3_0; s2_1 = s3_1; s2_2 = s3_2; s2_3 = s3_3; s2_4 = s3_4;
    s3_0 = s4_0; s3_1 = s4_1; s3_2 = s4_2; s3_3 = s4_3; s3_4 = s4_4;
    s4_0 = h0; s4_1 = h1; s4_2 = h2; s4_3 = h3; s4_4 = h4;

    const int z_out = zp - 2;
    if (z_out >= z0 && z_out <= zend) {
      const float sum_m = acc0, sum_f = acc1, sum_mm = acc2,
                  sum_ff = acc3, sum_mf = acc4;
      const float mmean = sum_m / NPIX;
      const float fmean = sum_f / NPIX;
      const float var_m = sum_mm - 2.0f * mmean * sum_m + NPIX * mmean * mmean;
      const float var_f = sum_ff - 2.0f * fmean * sum_f + NPIX * fmean * fmean;
      const float var_mf = var_m * var_f;
      const float cross =
          sum_mf - fmean * sum_m - mmean * sum_f + NPIX * mmean * fmean;

      const int lx = tx + 2, lyy = ty + 2;  // halo-2 offsets
      const int pc = z_out % 5;
      const int pm_ = (z_out + 4) % 5;
      const int pp_ = (z_out + 1) % 5;
      float2 c = ring[pc][lyy][lx];
      float mc = c.x - mmean, fc = c.y - fmean;

      bool valid =
          (var_mf > EPS) && (var_f > EPS) && (fc != 0.0f) && (mc != 0.0f);
      float factor = 0.0f;
      if (valid) factor = 2.0f * cross / var_mf * (mc - cross * fc / var_f);

      const size_t i = (size_t)z_out * SLICE + moff;
      const float u = ((cmm | cff) != 0) ? 1.0f : 0.0f;
      const float scale = -0.5f * factor * u;

      // jnp.gradient: central diff interior, one-sided edges.
      float gD, gH, gW;
      if (z_out == 0) {
        float2 a = ring[pp_][lyy][lx];
        gD = (a.x - c.x) + (a.y - c.y);
      } else if (z_out == DIM - 1) {
        float2 b = ring[pm_][lyy][lx];
        gD = (c.x - b.x) + (c.y - b.y);
      } else {
        float2 a = ring[pp_][lyy][lx];
        float2 b = ring[pm_][lyy][lx];
        gD = 0.5f * (a.x - b.x) + 0.5f * (a.y - b.y);
      }
      if (gy == 0) {
        float2 a = ring[pc][lyy + 1][lx];
        gH = (a.x - c.x) + (a.y - c.y);
      } else if (gy == DIM - 1) {
        float2 b = ring[pc][lyy - 1][lx];
        gH = (c.x - b.x) + (c.y - b.y);
      } else {
        float2 a = ring[pc][lyy + 1][lx];
        float2 b = ring[pc][lyy - 1][lx];
        gH = 0.5f * (a.x - b.x) + 0.5f * (a.y - b.y);
      }
      if (gx == 0) {
        float2 a = ring[pc][lyy][lx + 1];
        gW = (a.x - c.x) + (a.y - c.y);
      } else if (gx == DIM - 1) {
        float2 b = ring[pc][lyy][lx - 1];
        gW = (c.x - b.x) + (c.y - b.y);
      } else {
        float2 a = ring[pc][lyy][lx + 1];
        float2 b = ring[pc][lyy][lx - 1];
        gW = 0.5f * (a.x - b.x) + 0.5f * (a.y - b.y);
      }

      out[i] = scale * gD;
      out[(size_t)NV + i] = scale * gH;
      out[2 * (size_t)NV + i] = scale * gW;
    }
  }
}

extern "C" void kernel_launch(void* const* d_in, const int* in_sizes, int n_in,
                              void* d_out, int out_size) {
  const float* moving = (const float*)d_in[0];
  const float* fixed_ = (const float*)d_in[1];
  const int* mmask = (const int*)d_in[2];
  const int* fmask = (const int*)d_in[3];
  float* out = (float*)d_out;

  dim3 grid(DIM / TX, DIM / TY, DIM / ZCHUNK);  // 6 x 24 x 4 = 576 blocks
  ncc_fused<<<grid, 256>>>(moving, fixed_, mmask, fmask, out);
}

// round 12
// speedup vs baseline: 2.1219x; 1.1836x over previous
#include <cuda_runtime.h>
#include <cstdint>

#define DIM 192
#define SLICE (DIM * DIM)
#define NV (DIM * DIM * DIM)
#define NPIX 125.0f
#define EPS 1e-5f

#define TX 32
#define TY 8
#define ZCHUNK 64
#define NSTEPS (ZCHUNK + 4)   // 68 planes swept per chunk (halo 2 each side)

#define TLX (TX + 4)          // 36 (x halo 2)
#define TLY (TY + 4)          // 12 (y halo 2)
#define TLXP 37               // padded row
#define NSTAGE (TLX * TLY)    // 432 staging elements

__global__ void __launch_bounds__(256, 3) ncc_fused(
    const float* __restrict__ m, const float* __restrict__ f,
    const int* __restrict__ mmask, const int* __restrict__ fmask,
    float* __restrict__ out) {
  // 5-deep ring of (m,f) plane tiles with halo 2 — serves both the W-sum and
  // the z/y/x gradients. 5*12*37*8B = 17.8 KB.
  __shared__ float2 ring[5][TLY][TLXP];
  __shared__ float4 w4[TLY][TX];      // W-sums: m,f,mm,ff
  __shared__ float w1[TLY][TX + 1];   // W-sums: mf

  const int tid = threadIdx.x;
  const int tx = tid & 31;
  const int ty = tid >> 5;
  const int bx = blockIdx.x, by = blockIdx.y, bz = blockIdx.z;
  const int z0 = bz * ZCHUNK;
  const int zend = z0 + ZCHUNK - 1;
  const int gx = bx * TX + tx;
  const int gy = by * TY + ty;

  // Two staging slots per thread (NSTAGE=432, 256 threads).
  const int lx0 = tid % TLX, ly0 = tid / TLX;
  const int idx1 = tid + 256;
  const bool ok1 = idx1 < NSTAGE;
  const int lx1 = ok1 ? (idx1 % TLX) : 0, ly1 = ok1 ? (idx1 / TLX) : 0;
  const int ggx0 = bx * TX - 2 + lx0, ggy0 = by * TY - 2 + ly0;
  const int ggx1 = bx * TX - 2 + lx1, ggy1 = by * TY - 2 + ly1;
  const bool in0 = (unsigned)ggx0 < DIM && (unsigned)ggy0 < DIM;
  const bool in1 = ok1 && (unsigned)ggx1 < DIM && (unsigned)ggy1 < DIM;
  const size_t off0 = (size_t)ggy0 * DIM + ggx0;
  const size_t off1 = (size_t)ggy1 * DIM + ggx1;
  const size_t moff = (size_t)gy * DIM + gx;

  // W-sum assignments (384 points, 256 threads -> 1 + predicated 2nd).
  const int wxi0 = tid & 31, wly0 = tid >> 5;
  const int wxi1 = tid & 31, wly1 = (tid + 256) >> 5;
  const bool wok1 = (tid + 256) < TX * TLY;

  // Prefetch registers: next plane's data + next output's masks.
  float pa0 = 0.f, pb0 = 0.f, pa1 = 0.f, pb1 = 0.f;
  int pmm = 0, pff = 0;
  {
    const int zp = z0 - 2;  // plane for step 0
    if (zp >= 0) {
      const size_t pb_ = (size_t)zp * SLICE;
      if (in0) { pa0 = m[pb_ + off0]; pb0 = f[pb_ + off0]; }
      if (in1) { pa1 = m[pb_ + off1]; pb1 = f[pb_ + off1]; }
    }
  }

  // Sliding 5-plane D-window as shift registers (oldest = s0, newest = s4).
  float s0_0 = 0.f, s0_1 = 0.f, s0_2 = 0.f, s0_3 = 0.f, s0_4 = 0.f;
  float s1_0 = 0.f, s1_1 = 0.f, s1_2 = 0.f, s1_3 = 0.f, s1_4 = 0.f;
  float s2_0 = 0.f, s2_1 = 0.f, s2_2 = 0.f, s2_3 = 0.f, s2_4 = 0.f;
  float s3_0 = 0.f, s3_1 = 0.f, s3_2 = 0.f, s3_3 = 0.f, s3_4 = 0.f;
  float s4_0 = 0.f, s4_1 = 0.f, s4_2 = 0.f, s4_3 = 0.f, s4_4 = 0.f;
  float acc0 = 0.f, acc1 = 0.f, acc2 = 0.f, acc3 = 0.f, acc4 = 0.f;

  // Incrementally maintained base for the NEXT prefetch plane (z0-1 at entry).
  size_t nbase = (size_t)(z0 - 1) * SLICE;

#pragma unroll 1
  for (int step = 0; step < NSTEPS; step++) {
    const int zp = z0 - 2 + step;
    const bool active = (zp >= 0) && (zp < DIM);
    // Capture this step's masks before the prefetch overwrites them.
    const int cmm = pmm, cff = pff;
    float h0 = 0.f, h1 = 0.f, h2 = 0.f, h3 = 0.f, h4 = 0.f;

    if (active) {
      const int s = zp % 5;
      // Stage the prefetched plane into the ring slot.
      ring[s][ly0][lx0] = make_float2(pa0, pb0);
      if (ok1) ring[s][ly1][lx1] = make_float2(pa1, pb1);
      __syncthreads();
      // W-direction 5-tap sums of the 5 product fields (2 explicit passes).
      {
        float sm = 0.f, sf = 0.f, smm = 0.f, sff = 0.f, smf = 0.f;
#pragma unroll
        for (int d = 0; d < 5; d++) {
          float2 ab = ring[s][wly0][wxi0 + d];
          sm += ab.x;
          sf += ab.y;
          smm += ab.x * ab.x;
          sff += ab.y * ab.y;
          smf += ab.x * ab.y;
        }
        w4[wly0][wxi0] = make_float4(sm, sf, smm, sff);
        w1[wly0][wxi0] = smf;
      }
      if (wok1) {
        float sm = 0.f, sf = 0.f, smm = 0.f, sff = 0.f, smf = 0.f;
#pragma unroll
        for (int d = 0; d < 5; d++) {
          float2 ab = ring[s][wly1][wxi1 + d];
          sm += ab.x;
          sf += ab.y;
          smm += ab.x * ab.x;
          sff += ab.y * ab.y;
          smf += ab.x * ab.y;
        }
        w4[wly1][wxi1] = make_float4(sm, sf, smm, sff);
        w1[wly1][wxi1] = smf;
      }
    }

    // Prefetch next plane + next output's masks (overlaps the W-sum work).
    {
      const int zpn = zp + 1;
      if (step + 1 < NSTEPS && zpn >= 0 && zpn < DIM) {
        if (in0) { pa0 = m[nbase + off0]; pb0 = f[nbase + off0]; }
        if (in1) { pa1 = m[nbase + off1]; pb1 = f[nbase + off1]; }
      }
      const int zon = zpn - 2;
      if (zon >= z0 && zon <= zend) {
        const size_t mb = (size_t)zon * SLICE + moff;
        pmm = mmask[mb];
        pff = fmask[mb];
      }
      nbase += SLICE;
    }

    if (active) {
      __syncthreads();
      // H-direction 5-tap sums for this thread's (x,y).
#pragma unroll
      for (int d = 0; d < 5; d++) {
        float4 v = w4[ty + d][tx];
        h0 += v.x;
        h1 += v.y;
        h2 += v.z;
        h3 += v.w;
        h4 += w1[ty + d][tx];
      }
    }

    // Slide the D-window: add the new plane, drop the 5-steps-old plane.
    acc0 += h0 - s0_0; acc1 += h1 - s0_1; acc2 += h2 - s0_2;
    acc3 += h3 - s0_3; acc4 += h4 - s0_4;
    s0_0 = s1_0; s0_1 = s1_1; s0_2 = s1_2; s0_3 = s1_3; s0_4 = s1_4;
    s1_0 = s2_0; s1_1 = s2_1; s1_2 = s2_2; s1_3 = s2_3; s1_4 = s2_4;
    s2_0 = s3_0; s2_1 = s3_1; s2_2 = s3_2; s2_3 = s3_3; s2_4 = s3_4;
    s3_0 = s4_0; s3_1 = s4_1; s3_2 = s4_2; s3_3 = s4_3; s3_4 = s4_4;
    s4_0 = h0; s4_1 = h1; s4_2 = h2; s4_3 = h3; s4_4 = h4;

    const int z_out = zp - 2;
    if (z_out >= z0 && z_out <= zend) {
      const float sum_m = acc0, sum_f = acc1, sum_mm = acc2,
                  sum_ff = acc3, sum_mf = acc4;
      const float mmean = sum_m / NPIX;
      const float fmean = sum_f / NPIX;
      const float var_m = sum_mm - 2.0f * mmean * sum_m + NPIX * mmean * mmean;
      const float var_f = sum_ff - 2.0f * fmean * sum_f + NPIX * fmean * fmean;
      const float var_mf = var_m * var_f;
      const float cross =
          sum_mf - fmean * sum_m - mmean * sum_f + NPIX * mmean * fmean;

      const int lx = tx + 2, lyy = ty + 2;  // halo-2 offsets
      const int pc = z_out % 5;
      const int pm_ = (z_out + 4) % 5;
      const int pp_ = (z_out + 1) % 5;
      float2 c = ring[pc][lyy][lx];
      float mc = c.x - mmean, fc = c.y - fmean;

      bool valid =
          (var_mf > EPS) && (var_f > EPS) && (fc != 0.0f) && (mc != 0.0f);
      float factor = 0.0f;
      if (valid) factor = 2.0f * cross / var_mf * (mc - cross * fc / var_f);

      const size_t i = (size_t)z_out * SLICE + moff;
      const float u = ((cmm | cff) != 0) ? 1.0f : 0.0f;
      const float scale = -0.5f * factor * u;

      // jnp.gradient: central diff interior, one-sided edges.
      float gD, gH, gW;
      if (z_out == 0) {
        float2 a = ring[pp_][lyy][lx];
        gD = (a.x - c.x) + (a.y - c.y);
      } else if (z_out == DIM - 1) {
        float2 b = ring[pm_][lyy][lx];
        gD = (c.x - b.x) + (c.y - b.y);
      } else {
        float2 a = ring[pp_][lyy][lx];
        float2 b = ring[pm_][lyy][lx];
        gD = 0.5f * (a.x - b.x) + 0.5f * (a.y - b.y);
      }
      if (gy == 0) {
        float2 a = ring[pc][lyy + 1][lx];
        gH = (a.x - c.x) + (a.y - c.y);
      } else if (gy == DIM - 1) {
        float2 b = ring[pc][lyy - 1][lx];
        gH = (c.x - b.x) + (c.y - b.y);
      } else {
        float2 a = ring[pc][lyy + 1][lx];
        float2 b = ring[pc][lyy - 1][lx];
        gH = 0.5f * (a.x - b.x) + 0.5f * (a.y - b.y);
      }
      if (gx == 0) {
        float2 a = ring[pc][lyy][lx + 1];
        gW = (a.x - c.x) + (a.y - c.y);
      } else if (gx == DIM - 1) {
        float2 b = ring[pc][lyy][lx - 1];
        gW = (c.x - b.x) + (c.y - b.y);
      } else {
        float2 a = ring[pc][lyy][lx + 1];
        float2 b = ring[pc][lyy][lx - 1];
        gW = 0.5f * (a.x - b.x) + 0.5f * (a.y - b.y);
      }

      out[i] = scale * gD;
      out[(size_t)NV + i] = scale * gH;
      out[2 * (size_t)NV + i] = scale * gW;
    }
  }
}

extern "C" void kernel_launch(void* const* d_in, const int* in_sizes, int n_in,
                              void* d_out, int out_size) {
  const float* moving = (const float*)d_in[0];
  const float* fixed_ = (const float*)d_in[1];
  const int* mmask = (const int*)d_in[2];
  const int* fmask = (const int*)d_in[3];
  float* out = (float*)d_out;

  dim3 grid(DIM / TX, DIM / TY, DIM / ZCHUNK);  // 6 x 24 x 3 = 432 blocks
  ncc_fused<<<grid, 256>>>(moving, fixed_, mmask, fmask, out);
}